// round 15
// baseline (speedup 1.0000x reference)
#include <cuda_runtime.h>
#include <cuda_bf16.h>
#include <cuda_fp16.h>

#define BB 2
#define SS 2048
#define EE 1024
#define HH 16
#define HD 64
#define MM (BB*SS)   // 4096
#define SCALE 0.03125f      // 1/sqrt(1024)
#define WSC 1024.0f         // weight prescale (2^10)
#define ASC 32.0f           // attention-output prescale (2^5)

// ---------------------------------------------------------------------------
// Scratch (__device__ globals — allocation-free)
// ---------------------------------------------------------------------------
__device__ __half g_Xh[3*MM*EE];                   // inputs, fp16 hi only
__device__ __half g_Wh[4*EE*EE];                   // weights, fp16 hi only, x1024
__device__ __half g_Qh[BB*HH*SS*HD];               // pre-scaled by 1/32
__device__ __half g_Kh[BB*HH*SS*HD];
__device__ __half g_Vh[BB*HH*SS*HD];
__device__ __half g_Ah[MM*EE], g_Al[MM*EE];        // attn out, fp16 split, x32
__device__ unsigned g_bm[SS*SS/32];

// ---------------------------------------------------------------------------
// Helpers
// ---------------------------------------------------------------------------
__device__ __forceinline__ unsigned smem_u32(const void* p) {
    unsigned a;
    asm("{ .reg .u64 t; cvta.to.shared.u64 t, %1; cvt.u32.u64 %0, t; }" : "=r"(a) : "l"(p));
    return a;
}
__device__ __forceinline__ void ldm4(unsigned& r0, unsigned& r1, unsigned& r2, unsigned& r3, unsigned addr) {
    asm volatile("ldmatrix.sync.aligned.m8n8.x4.shared.b16 {%0,%1,%2,%3}, [%4];"
                 : "=r"(r0), "=r"(r1), "=r"(r2), "=r"(r3) : "r"(addr));
}
__device__ __forceinline__ void ldm4t(unsigned& r0, unsigned& r1, unsigned& r2, unsigned& r3, unsigned addr) {
    asm volatile("ldmatrix.sync.aligned.m8n8.x4.trans.shared.b16 {%0,%1,%2,%3}, [%4];"
                 : "=r"(r0), "=r"(r1), "=r"(r2), "=r"(r3) : "r"(addr));
}
__device__ __forceinline__ void mma16816h(float* c, const unsigned* a, const unsigned* b) {
    asm volatile(
        "mma.sync.aligned.m16n8k16.row.col.f32.f16.f16.f32 "
        "{%0,%1,%2,%3}, {%4,%5,%6,%7}, {%8,%9}, {%0,%1,%2,%3};"
        : "+f"(c[0]), "+f"(c[1]), "+f"(c[2]), "+f"(c[3])
        : "r"(a[0]), "r"(a[1]), "r"(a[2]), "r"(a[3]), "r"(b[0]), "r"(b[1]));
}
__device__ __forceinline__ void cp16(unsigned dst, const void* src) {
    asm volatile("cp.async.cg.shared.global [%0], [%1], 16;" :: "r"(dst), "l"(src) : "memory");
}
// fp16 split pack
__device__ __forceinline__ void packsplith(unsigned& h, unsigned& l, float x, float y) {
    __half hx = __float2half_rn(x), hy = __float2half_rn(y);
    __half lx = __float2half_rn(x - __half2float(hx));
    __half ly = __float2half_rn(y - __half2float(hy));
    __half2 H = __halves2half2(hx, hy), L = __halves2half2(lx, ly);
    h = *reinterpret_cast<unsigned*>(&H);
    l = *reinterpret_cast<unsigned*>(&L);
}

// ---------------------------------------------------------------------------
// mask int32 [S*S] -> bitmask
// ---------------------------------------------------------------------------
__global__ __launch_bounds__(256) void bm_kernel(const int* __restrict__ mask) {
    const int i = blockIdx.x * 256 + threadIdx.x;
    unsigned b = __ballot_sync(0xffffffffu, mask[i] != 0);
    if ((i & 31) == 0) g_bm[i >> 5] = b;
}

// ---------------------------------------------------------------------------
// fp32 -> fp16 (inputs, fused q/k/v via blockIdx.y)
// ---------------------------------------------------------------------------
__global__ __launch_bounds__(256) void cvtx_kernel(const float* __restrict__ q,
                                                   const float* __restrict__ k,
                                                   const float* __restrict__ v)
{
    const float* src = (blockIdx.y == 0) ? q : (blockIdx.y == 1) ? k : v;
    __half* hi = g_Xh + (size_t)blockIdx.y * MM * EE;
    const size_t i = (size_t)(blockIdx.x * 256 + threadIdx.x) * 4;
    float4 val = *(const float4*)(src + i);
    *reinterpret_cast<__half2*>(&hi[i])     = __floats2half2_rn(val.x, val.y);
    *reinterpret_cast<__half2*>(&hi[i + 2]) = __floats2half2_rn(val.z, val.w);
}

// fp32 -> fp16, prescaled x1024 (weights, fused via blockIdx.y)
__global__ __launch_bounds__(256) void cvtw_kernel(const float* __restrict__ wq,
                                                   const float* __restrict__ wk,
                                                   const float* __restrict__ wv,
                                                   const float* __restrict__ wo)
{
    const float* src = (blockIdx.y == 0) ? wq : (blockIdx.y == 1) ? wk :
                       (blockIdx.y == 2) ? wv : wo;
    __half* hi = g_Wh + (size_t)blockIdx.y * EE * EE;
    const size_t i = (size_t)(blockIdx.x * 256 + threadIdx.x) * 4;
    float4 val = *(const float4*)(src + i);
    *reinterpret_cast<__half2*>(&hi[i])     = __floats2half2_rn(val.x * WSC, val.y * WSC);
    *reinterpret_cast<__half2*>(&hi[i + 2]) = __floats2half2_rn(val.z * WSC, val.w * WSC);
}

// ---------------------------------------------------------------------------
// HMMA fp16 GEMM, NT A-terms: C = (Ah[+Al]) @ Bh^T  (B prescaled x1024)
// CTA 256 thr (8 warps 2x4), tile 128x256, warp tile 64x64, K-chunk 32,
// double-buffered. NT=1: sel 0/1/2 -> Q/K/V planes. NT=2: sel 3 -> fp32 out.
// ---------------------------------------------------------------------------
#define KC 32
#define RS 40
#define A_BY (128*RS*2)               // 10240
#define B_BY (256*RS*2)               // 20480

template<int NT>
__global__ __launch_bounds__(256) void mm_kernel(int sel_base, float* __restrict__ out_ext,
                                                 const float* __restrict__ bias)
{
    extern __shared__ __half smM[];
    const unsigned sb = smem_u32(smM);
    constexpr unsigned STB = NT * A_BY + B_BY;

    const int tid = threadIdx.x;
    const int wid = tid >> 5, lane = tid & 31;
    const int wm = wid >> 2, wn = wid & 3;            // 2 x 4 warp grid
    const int m0 = blockIdx.y * 128, n0 = blockIdx.x * 256;
    const int sel = sel_base + blockIdx.z;

    const __half* Ahp = (NT == 1) ? g_Xh + (size_t)sel * MM * EE : g_Ah;
    const __half* Alp = (NT == 2) ? g_Al : (const __half*)0;
    const __half* Bhp = g_Wh + (size_t)sel * EE * EE;

    float acc[32][4];                                  // 4 m-tiles x 8 n-tiles
    #pragma unroll
    for (int i = 0; i < 32; i++)
        #pragma unroll
        for (int j = 0; j < 4; j++) acc[i][j] = 0.f;

    const int r  = tid >> 2;        // 0..63
    const int ch = tid & 3;

    auto load_stage = [&](int c, int s) {
        const unsigned base = sb + s * STB;
        const __half* Asrc0 = Ahp + (size_t)m0 * EE + c * KC;
        #pragma unroll
        for (int i2 = 0; i2 < 2; i2++) {
            const int row = i2 * 64 + r;
            cp16(base + row * (RS*2) + ch * 16, Asrc0 + (size_t)row * EE + ch * 8);
        }
        if (NT == 2) {
            const __half* Asrc1 = Alp + (size_t)m0 * EE + c * KC;
            #pragma unroll
            for (int i2 = 0; i2 < 2; i2++) {
                const int row = i2 * 64 + r;
                cp16(base + A_BY + row * (RS*2) + ch * 16, Asrc1 + (size_t)row * EE + ch * 8);
            }
        }
        const __half* Bsrc = Bhp + (size_t)n0 * EE + c * KC;
        const unsigned bbase = base + NT * A_BY;
        #pragma unroll
        for (int i2 = 0; i2 < 4; i2++) {
            const int row = i2 * 64 + r;
            cp16(bbase + row * (RS*2) + ch * 16, Bsrc + (size_t)row * EE + ch * 8);
        }
        asm volatile("cp.async.commit_group;" ::: "memory");
    };

    load_stage(0, 0);

    for (int c = 0; c < EE / KC; c++) {
        if (c + 1 < EE / KC) {
            load_stage(c + 1, (c + 1) & 1);
            asm volatile("cp.async.wait_group 1;" ::: "memory");
        } else {
            asm volatile("cp.async.wait_group 0;" ::: "memory");
        }
        __syncthreads();

        const unsigned st = sb + (c & 1) * STB;
        const unsigned aH = st;
        const unsigned aL = st + A_BY;                // valid only when NT==2
        const unsigned bH = st + NT * A_BY;

        #pragma unroll
        for (int kk = 0; kk < KC; kk += 16) {
            unsigned ah[4][4], al[4][4];
            #pragma unroll
            for (int i = 0; i < 4; i++) {
                const int row = wm * 64 + 16 * i + (lane & 15);
                const unsigned off = row * (RS*2) + (kk + (lane >> 4) * 8) * 2;
                ldm4(ah[i][0], ah[i][1], ah[i][2], ah[i][3], aH + off);
                if (NT == 2)
                    ldm4(al[i][0], al[i][1], al[i][2], al[i][3], aL + off);
            }
            unsigned bh[8][2];
            #pragma unroll
            for (int p = 0; p < 4; p++) {
                const int g = lane >> 3;
                const int row = wn * 64 + 16 * p + ((g >> 1) << 3) + (lane & 7);
                const unsigned off = row * (RS*2) + (kk + (g & 1) * 8) * 2;
                ldm4(bh[2*p][0], bh[2*p][1], bh[2*p+1][0], bh[2*p+1][1], bH + off);
            }
            #pragma unroll
            for (int i = 0; i < 4; i++)
                #pragma unroll
                for (int j = 0; j < 8; j++) {
                    mma16816h(acc[i*8+j], ah[i], bh[j]);
                    if (NT == 2)
                        mma16816h(acc[i*8+j], al[i], bh[j]);
                }
        }
        __syncthreads();
    }

    const float DSC  = 1.0f / WSC;            // descale weights
    const float DSCO = 1.0f / (WSC * ASC);    // descale weights + A prescale

    #pragma unroll
    for (int i = 0; i < 4; i++) {
        #pragma unroll
        for (int j = 0; j < 8; j++) {
            const int n = n0 + wn * 64 + 8 * j + (lane & 3) * 2;
            #pragma unroll
            for (int hrow = 0; hrow < 2; hrow++) {
                const int m = m0 + wm * 64 + 16 * i + (lane >> 2) + hrow * 8;
                float2 val = make_float2(acc[i*8+j][hrow*2+0], acc[i*8+j][hrow*2+1]);
                if (NT == 1) {
                    val.x *= DSC; val.y *= DSC;
                    const int b = m >> 11, s = m & (SS - 1);
                    const int h = n >> 6, dd = n & 63;
                    const size_t off = (((size_t)b * HH + h) * SS + s) * HD + dd;
                    if (sel == 0) {
                        *reinterpret_cast<__half2*>(&g_Qh[off]) =
                            __floats2half2_rn(val.x * SCALE, val.y * SCALE);
                    } else if (sel == 1) {
                        *reinterpret_cast<__half2*>(&g_Kh[off]) = __floats2half2_rn(val.x, val.y);
                    } else {
                        *reinterpret_cast<__half2*>(&g_Vh[off]) = __floats2half2_rn(val.x, val.y);
                    }
                } else {
                    val.x = val.x * DSCO + bias[n];
                    val.y = val.y * DSCO + bias[n + 1];
                    *(float2*)(out_ext + (size_t)m * EE + n) = val;
                }
            }
        }
    }
}

// ---------------------------------------------------------------------------
// Tensor-core flash attention: fp16 1-term QK^T, fp16 1-term PV,
// no-max softmax. Grid (SS/128, HH, BB), 128 thr (4 warps x 32 q-rows),
// 2 CTAs/SM.
// ---------------------------------------------------------------------------
#define RSA 72
#define QPL (128*RSA*2)        // 18432 B  (Q fp16, pre-scaled)
#define KPL (64*RSA*2)         // 9216 B per K/V plane
#define STG (2*KPL)            // 18432 B per stage (Kh, Vh)
#define ASMEM (QPL + 2*STG)    // 55296 B

__global__ __launch_bounds__(128, 2) void attn_kernel()
{
    extern __shared__ __half smA[];
    const unsigned sb = smem_u32(smA);
    const int tid = threadIdx.x, wid = tid >> 5, lane = tid & 31;
    const int q0 = blockIdx.x * 128, h = blockIdx.y, b = blockIdx.z;
    const size_t head = ((size_t)b * HH + h) * SS * HD;

    const __half* Qp  = g_Qh + head + (size_t)q0 * HD;
    const __half* Khp = g_Kh + head;
    const __half* Vhp = g_Vh + head;

    #define LOAD_KV(t, s) do {                                                  \
        const int _k0 = (t) * 64;                                               \
        const __half* _pl[2] = {Khp, Vhp};                                      \
        const unsigned _b = sb + QPL + (s) * STG;                               \
        _Pragma("unroll")                                                       \
        for (int _it = 0; _it < 8; _it++) {                                     \
            const int _c = _it * 128 + tid;                                     \
            const int _p = _c >> 9, _r = (_c >> 3) & 63, _ch = _c & 7;          \
            cp16(_b + _p * KPL + _r * (RSA*2) + _ch * 16,                       \
                 _pl[_p] + (size_t)(_k0 + _r) * HD + _ch * 8);                  \
        }                                                                       \
        asm volatile("cp.async.commit_group;" ::: "memory");                    \
    } while (0)

    // prologue: Q plane + stage 0
    #pragma unroll
    for (int it = 0; it < 8; it++) {
        const int c = it * 128 + tid;          // 0..1023
        const int row = (c >> 3) & 127, ch = c & 7;
        cp16(sb + row * (RSA*2) + ch * 16, Qp + (size_t)row * HD + ch * 8);
    }
    LOAD_KV(0, 0);

    float o[16][4];                    // [i*8+u]: 2 m-tiles x 8 d-tiles
    #pragma unroll
    for (int u = 0; u < 16; u++)
        #pragma unroll
        for (int j = 0; j < 4; j++) o[u][j] = 0.f;
    float rs[2][2] = {};               // [m-tile][hrow]
    unsigned qh[2][4][4];              // [m-tile][kk][frag]

    const int rbase = q0 + wid * 32 + (lane >> 2);

    for (int t = 0; t < SS / 64; t++) {
        if (t + 1 < SS / 64) {
            LOAD_KV(t + 1, (t + 1) & 1);
            asm volatile("cp.async.wait_group 1;" ::: "memory");
        } else {
            asm volatile("cp.async.wait_group 0;" ::: "memory");
        }
        __syncthreads();

        if (t == 0) {   // Q fragments -> registers, once
            #pragma unroll
            for (int i = 0; i < 2; i++)
                #pragma unroll
                for (int kk = 0; kk < 4; kk++) {
                    const int row = wid * 32 + i * 16 + (lane & 15);
                    const unsigned off = row * (RSA*2) + (kk * 16 + (lane >> 4) * 8) * 2;
                    ldm4(qh[i][kk][0], qh[i][kk][1], qh[i][kk][2], qh[i][kk][3], sb + off);
                }
        }

        const unsigned st = sb + QPL + (t & 1) * STG;
        uint2 mw[2][2];
        #pragma unroll
        for (int i = 0; i < 2; i++)
            #pragma unroll
            for (int hr = 0; hr < 2; hr++)
                mw[i][hr] = *(const uint2*)&g_bm[(rbase + i * 16 + hr * 8) * (SS/32) + t * 2];

        // ---- S = Q K^T ----
        float s[16][4];                // [i*8+j]
        #pragma unroll
        for (int j = 0; j < 16; j++)
            #pragma unroll
            for (int e = 0; e < 4; e++) s[j][e] = 0.f;

        #pragma unroll
        for (int kk = 0; kk < 4; kk++) {
            unsigned bh[8][2];
            #pragma unroll
            for (int p = 0; p < 4; p++) {
                const int g = lane >> 3;
                const int row = p * 16 + ((g >> 1) << 3) + (lane & 7);
                const unsigned off = row * (RSA*2) + (kk * 16 + (g & 1) * 8) * 2;
                ldm4(bh[2*p][0], bh[2*p][1], bh[2*p+1][0], bh[2*p+1][1], st + off);
            }
            #pragma unroll
            for (int i = 0; i < 2; i++)
                #pragma unroll
                for (int j = 0; j < 8; j++)
                    mma16816h(s[i*8+j], qh[i][kk], bh[j]);
        }

        // ---- softmax numerator ----
        #pragma unroll
        for (int i = 0; i < 2; i++)
            #pragma unroll
            for (int j = 0; j < 8; j++) {
                float* sv = s[i*8+j];
                const int sh = (8 * j + (lane & 3) * 2) & 31;
                const unsigned wA = (j < 4) ? mw[i][0].x : mw[i][0].y;
                const unsigned wB = (j < 4) ? mw[i][1].x : mw[i][1].y;
                sv[0] = (float)((wA >> sh) & 1u)       * __expf(sv[0]);
                sv[1] = (float)((wA >> (sh + 1)) & 1u) * __expf(sv[1]);
                sv[2] = (float)((wB >> sh) & 1u)       * __expf(sv[2]);
                sv[3] = (float)((wB >> (sh + 1)) & 1u) * __expf(sv[3]);
                rs[i][0] += sv[0] + sv[1];
                rs[i][1] += sv[2] + sv[3];
            }

        // ---- O += P V  (fp16 1-term) ----
        #pragma unroll
        for (int t16 = 0; t16 < 4; t16++) {
            unsigned ph[2][4];
            #pragma unroll
            for (int i = 0; i < 2; i++) {
                const float* s0 = s[i*8 + 2*t16];
                const float* s1 = s[i*8 + 2*t16 + 1];
                __half2 a  = __floats2half2_rn(s0[0], s0[1]);
                __half2 b2 = __floats2half2_rn(s0[2], s0[3]);
                __half2 c2 = __floats2half2_rn(s1[0], s1[1]);
                __half2 d2 = __floats2half2_rn(s1[2], s1[3]);
                ph[i][0] = *reinterpret_cast<unsigned*>(&a);
                ph[i][1] = *reinterpret_cast<unsigned*>(&b2);
                ph[i][2] = *reinterpret_cast<unsigned*>(&c2);
                ph[i][3] = *reinterpret_cast<unsigned*>(&d2);
            }
            #pragma unroll
            for (int u2 = 0; u2 < 4; u2++) {
                unsigned vh[2][2];
                const int g = lane >> 3;
                const int row = t16 * 16 + (g & 1) * 8 + (lane & 7);
                const unsigned off = row * (RSA*2) + (u2 * 16 + (g >> 1) * 8) * 2;
                ldm4t(vh[0][0], vh[0][1], vh[1][0], vh[1][1], st + KPL + off);
                #pragma unroll
                for (int i = 0; i < 2; i++) {
                    mma16816h(o[i*8 + 2*u2],     ph[i], vh[0]);
                    mma16816h(o[i*8 + 2*u2 + 1], ph[i], vh[1]);
                }
            }
        }
        __syncthreads();
    }

    // ---- normalize + write fp16 split (x32) to g_Ah/g_Al ----
    #pragma unroll
    for (int i = 0; i < 2; i++)
        #pragma unroll
        for (int hr = 0; hr < 2; hr++) {
            rs[i][hr] += __shfl_xor_sync(0xffffffffu, rs[i][hr], 1);
            rs[i][hr] += __shfl_xor_sync(0xffffffffu, rs[i][hr], 2);
        }

    #pragma unroll
    for (int i = 0; i < 2; i++) {
        #pragma unroll
        for (int hr = 0; hr < 2; hr++) {
            const float inv = ASC / rs[i][hr];
            const int rrow = rbase + i * 16 + hr * 8;
            const size_t mr = (size_t)(b * SS + rrow) * EE + h * 64;
            #pragma unroll
            for (int u = 0; u < 8; u++) {
                const int c = 8 * u + (lane & 3) * 2;
                unsigned hu, lu;
                packsplith(hu, lu, o[i*8+u][hr*2+0] * inv, o[i*8+u][hr*2+1] * inv);
                *reinterpret_cast<unsigned*>(&g_Ah[mr + c]) = hu;
                *reinterpret_cast<unsigned*>(&g_Al[mr + c]) = lu;
            }
        }
    }
}

// ---------------------------------------------------------------------------
extern "C" void kernel_launch(void* const* d_in, const int* in_sizes, int n_in,
                              void* d_out, int out_size)
{
    const float* q    = (const float*)d_in[0];
    const float* k    = (const float*)d_in[1];
    const float* v    = (const float*)d_in[2];
    const int*   mask = (const int*)  d_in[3];
    const float* wq   = (const float*)d_in[4];
    const float* wk   = (const float*)d_in[5];
    const float* wv   = (const float*)d_in[6];
    const float* wo   = (const float*)d_in[7];
    const float* bo   = (const float*)d_in[8];
    float* out = (float*)d_out;

    const int SM1 = 2 * (1 * A_BY + B_BY);   // 61440
    const int SM2 = 2 * (2 * A_BY + B_BY);   // 81920

    cudaFuncSetAttribute(mm_kernel<1>, cudaFuncAttributeMaxDynamicSharedMemorySize, SM1);
    cudaFuncSetAttribute(mm_kernel<2>, cudaFuncAttributeMaxDynamicSharedMemorySize, SM2);
    cudaFuncSetAttribute(attn_kernel,  cudaFuncAttributeMaxDynamicSharedMemorySize, ASMEM);

    bm_kernel<<<SS*SS/256, 256>>>(mask);

    dim3 gx(MM*EE/1024, 3);
    cvtx_kernel<<<gx, 256>>>(q, k, v);
    dim3 gw(EE*EE/1024, 4);
    cvtw_kernel<<<gw, 256>>>(wq, wk, wv, wo);

    // Q/K/V projections: 1-term fp16, 128x256 tiles
    dim3 gp(EE/256, MM/128, 3);
    mm_kernel<1><<<gp, 256, SM1>>>(0, nullptr, bo);

    // Attention
    dim3 ga(SS/128, HH, BB);
    attn_kernel<<<ga, 128, ASMEM>>>();

    // Output projection: 2-term fp16 + bias
    dim3 go(EE/256, MM/128, 1);
    mm_kernel<2><<<go, 256, SM2>>>(3, out, bo);
}

// round 16
// speedup vs baseline: 1.5880x; 1.5880x over previous
#include <cuda_runtime.h>
#include <cuda_bf16.h>
#include <cuda_fp16.h>

#define BB 2
#define SS 2048
#define EE 1024
#define HH 16
#define HD 64
#define MM (BB*SS)   // 4096
#define SCALE 0.03125f      // 1/sqrt(1024)
#define WSC 1024.0f         // weight prescale (2^10)
#define ASC 32.0f           // attention-output prescale (2^5)

// ---------------------------------------------------------------------------
// Scratch (__device__ globals — allocation-free)
// ---------------------------------------------------------------------------
__device__ __half g_Xh[3*MM*EE];                   // inputs, fp16
__device__ __half g_Wh[4*EE*EE];                   // weights, fp16, x1024
__device__ __half g_Qh[BB*HH*SS*HD];               // pre-scaled by 1/32
__device__ __half g_Kh[BB*HH*SS*HD];
__device__ __half g_Vh[BB*HH*SS*HD];
__device__ __half g_Ah[MM*EE];                     // attn out, fp16, x32
__device__ unsigned g_bm[SS*SS/32];

// ---------------------------------------------------------------------------
// Helpers
// ---------------------------------------------------------------------------
__device__ __forceinline__ unsigned smem_u32(const void* p) {
    unsigned a;
    asm("{ .reg .u64 t; cvta.to.shared.u64 t, %1; cvt.u32.u64 %0, t; }" : "=r"(a) : "l"(p));
    return a;
}
__device__ __forceinline__ void ldm4(unsigned& r0, unsigned& r1, unsigned& r2, unsigned& r3, unsigned addr) {
    asm volatile("ldmatrix.sync.aligned.m8n8.x4.shared.b16 {%0,%1,%2,%3}, [%4];"
                 : "=r"(r0), "=r"(r1), "=r"(r2), "=r"(r3) : "r"(addr));
}
__device__ __forceinline__ void ldm4t(unsigned& r0, unsigned& r1, unsigned& r2, unsigned& r3, unsigned addr) {
    asm volatile("ldmatrix.sync.aligned.m8n8.x4.trans.shared.b16 {%0,%1,%2,%3}, [%4];"
                 : "=r"(r0), "=r"(r1), "=r"(r2), "=r"(r3) : "r"(addr));
}
__device__ __forceinline__ void mma16816h(float* c, const unsigned* a, const unsigned* b) {
    asm volatile(
        "mma.sync.aligned.m16n8k16.row.col.f32.f16.f16.f32 "
        "{%0,%1,%2,%3}, {%4,%5,%6,%7}, {%8,%9}, {%0,%1,%2,%3};"
        : "+f"(c[0]), "+f"(c[1]), "+f"(c[2]), "+f"(c[3])
        : "r"(a[0]), "r"(a[1]), "r"(a[2]), "r"(a[3]), "r"(b[0]), "r"(b[1]));
}
__device__ __forceinline__ void cp16(unsigned dst, const void* src) {
    asm volatile("cp.async.cg.shared.global [%0], [%1], 16;" :: "r"(dst), "l"(src) : "memory");
}

// ---------------------------------------------------------------------------
// mask int32 [S*S] -> bitmask
// ---------------------------------------------------------------------------
__global__ __launch_bounds__(256) void bm_kernel(const int* __restrict__ mask) {
    const int i = blockIdx.x * 256 + threadIdx.x;
    unsigned b = __ballot_sync(0xffffffffu, mask[i] != 0);
    if ((i & 31) == 0) g_bm[i >> 5] = b;
}

// ---------------------------------------------------------------------------
// fp32 -> fp16 (inputs, fused q/k/v via blockIdx.y)
// ---------------------------------------------------------------------------
__global__ __launch_bounds__(256) void cvtx_kernel(const float* __restrict__ q,
                                                   const float* __restrict__ k,
                                                   const float* __restrict__ v)
{
    const float* src = (blockIdx.y == 0) ? q : (blockIdx.y == 1) ? k : v;
    __half* hi = g_Xh + (size_t)blockIdx.y * MM * EE;
    const size_t i = (size_t)(blockIdx.x * 256 + threadIdx.x) * 4;
    float4 val = *(const float4*)(src + i);
    *reinterpret_cast<__half2*>(&hi[i])     = __floats2half2_rn(val.x, val.y);
    *reinterpret_cast<__half2*>(&hi[i + 2]) = __floats2half2_rn(val.z, val.w);
}

// fp32 -> fp16, prescaled x1024 (weights, fused via blockIdx.y)
__global__ __launch_bounds__(256) void cvtw_kernel(const float* __restrict__ wq,
                                                   const float* __restrict__ wk,
                                                   const float* __restrict__ wv,
                                                   const float* __restrict__ wo)
{
    const float* src = (blockIdx.y == 0) ? wq : (blockIdx.y == 1) ? wk :
                       (blockIdx.y == 2) ? wv : wo;
    __half* hi = g_Wh + (size_t)blockIdx.y * EE * EE;
    const size_t i = (size_t)(blockIdx.x * 256 + threadIdx.x) * 4;
    float4 val = *(const float4*)(src + i);
    *reinterpret_cast<__half2*>(&hi[i])     = __floats2half2_rn(val.x * WSC, val.y * WSC);
    *reinterpret_cast<__half2*>(&hi[i + 2]) = __floats2half2_rn(val.z * WSC, val.w * WSC);
}

// ---------------------------------------------------------------------------
// HMMA fp16 1-term GEMM: C = A @ B^T  (B prescaled x1024)
// CTA 256 thr (8 warps 2x4), tile 128x128, warp tile 64x32, K-chunk 32,
// double-buffered, 2 CTAs/SM.
// sel 0/1/2: A = X plane -> Q/K/V fp16 planes.  sel 3: A = g_Ah -> fp32 out.
// ---------------------------------------------------------------------------
#define KC 32
#define RS 40
#define TILE_BYTES (128*RS*2)         // 10240
#define STB (2*TILE_BYTES)            // 20480 per stage (A, B)
#define SMEM_MM (2*STB)               // 40960

__global__ __launch_bounds__(256, 2) void mm_kernel(int sel_base, float* __restrict__ out_ext,
                                                    const float* __restrict__ bias)
{
    extern __shared__ __half smM[];
    const unsigned sb = smem_u32(smM);

    const int tid = threadIdx.x;
    const int wid = tid >> 5, lane = tid & 31;
    const int wm = wid >> 2, wn = wid & 3;
    const int m0 = blockIdx.y * 128, n0 = blockIdx.x * 128;
    const int sel = sel_base + blockIdx.z;

    const __half* Ahp = (sel < 3) ? g_Xh + (size_t)sel * MM * EE : g_Ah;
    const __half* Bhp = g_Wh + (size_t)sel * EE * EE;

    float acc[16][4];
    #pragma unroll
    for (int i = 0; i < 16; i++)
        #pragma unroll
        for (int j = 0; j < 4; j++) acc[i][j] = 0.f;

    const int r  = tid >> 2;        // 0..63
    const int ch = tid & 3;

    auto load_stage = [&](int c, int s) {
        const unsigned base = sb + s * STB;
        const __half* Asrc = Ahp + (size_t)m0 * EE + c * KC;
        const __half* Bsrc = Bhp + (size_t)n0 * EE + c * KC;
        #pragma unroll
        for (int i2 = 0; i2 < 2; i2++) {
            const int row = i2 * 64 + r;
            cp16(base + row * (RS*2) + ch * 16, Asrc + (size_t)row * EE + ch * 8);
            cp16(base + TILE_BYTES + row * (RS*2) + ch * 16, Bsrc + (size_t)row * EE + ch * 8);
        }
        asm volatile("cp.async.commit_group;" ::: "memory");
    };

    load_stage(0, 0);

    for (int c = 0; c < EE / KC; c++) {
        if (c + 1 < EE / KC) {
            load_stage(c + 1, (c + 1) & 1);
            asm volatile("cp.async.wait_group 1;" ::: "memory");
        } else {
            asm volatile("cp.async.wait_group 0;" ::: "memory");
        }
        __syncthreads();

        const unsigned st = sb + (c & 1) * STB;
        const unsigned aH = st;
        const unsigned bH = st + TILE_BYTES;

        #pragma unroll
        for (int kk = 0; kk < KC; kk += 16) {
            unsigned ah[4][4];
            #pragma unroll
            for (int i = 0; i < 4; i++) {
                const int row = wm * 64 + 16 * i + (lane & 15);
                const unsigned off = row * (RS*2) + (kk + (lane >> 4) * 8) * 2;
                ldm4(ah[i][0], ah[i][1], ah[i][2], ah[i][3], aH + off);
            }
            unsigned bh[4][2];
            #pragma unroll
            for (int p = 0; p < 2; p++) {
                const int g = lane >> 3;
                const int row = wn * 32 + 16 * p + ((g >> 1) << 3) + (lane & 7);
                const unsigned off = row * (RS*2) + (kk + (g & 1) * 8) * 2;
                ldm4(bh[2*p][0], bh[2*p][1], bh[2*p+1][0], bh[2*p+1][1], bH + off);
            }
            #pragma unroll
            for (int i = 0; i < 4; i++)
                #pragma unroll
                for (int j = 0; j < 4; j++)
                    mma16816h(acc[i*4+j], ah[i], bh[j]);
        }
        __syncthreads();
    }

    const float DSC  = 1.0f / WSC;            // descale weights
    const float DSCO = 1.0f / (WSC * ASC);    // descale weights + A prescale

    #pragma unroll
    for (int i = 0; i < 4; i++) {
        #pragma unroll
        for (int j = 0; j < 4; j++) {
            const int n = n0 + wn * 32 + 8 * j + (lane & 3) * 2;
            #pragma unroll
            for (int hrow = 0; hrow < 2; hrow++) {
                const int m = m0 + wm * 64 + 16 * i + (lane >> 2) + hrow * 8;
                float2 val = make_float2(acc[i*4+j][hrow*2+0], acc[i*4+j][hrow*2+1]);
                if (sel < 3) {
                    val.x *= DSC; val.y *= DSC;
                    const int b = m >> 11, s = m & (SS - 1);
                    const int h = n >> 6, dd = n & 63;
                    const size_t off = (((size_t)b * HH + h) * SS + s) * HD + dd;
                    if (sel == 0) {
                        *reinterpret_cast<__half2*>(&g_Qh[off]) =
                            __floats2half2_rn(val.x * SCALE, val.y * SCALE);
                    } else if (sel == 1) {
                        *reinterpret_cast<__half2*>(&g_Kh[off]) = __floats2half2_rn(val.x, val.y);
                    } else {
                        *reinterpret_cast<__half2*>(&g_Vh[off]) = __floats2half2_rn(val.x, val.y);
                    }
                } else {
                    val.x = val.x * DSCO + bias[n];
                    val.y = val.y * DSCO + bias[n + 1];
                    *(float2*)(out_ext + (size_t)m * EE + n) = val;
                }
            }
        }
    }
}

// ---------------------------------------------------------------------------
// Tensor-core flash attention: fp16 1-term QK^T, fp16 1-term PV,
// no-max softmax. Grid (SS/128, HH, BB), 256 thr (8 warps x 16 q-rows),
// 2 CTAs/SM.  (Exact R14-benched configuration, minus the g_Al plane.)
// ---------------------------------------------------------------------------
#define RSA 72
#define QPL (128*RSA*2)        // 18432 B  (Q fp16, pre-scaled)
#define KPL (64*RSA*2)         // 9216 B per K/V plane
#define STG (2*KPL)            // 18432 B per stage (Kh, Vh)
#define ASMEM (QPL + 2*STG)    // 55296 B

__global__ __launch_bounds__(256, 2) void attn_kernel()
{
    extern __shared__ __half smA[];
    const unsigned sb = smem_u32(smA);
    const int tid = threadIdx.x, wid = tid >> 5, lane = tid & 31;
    const int q0 = blockIdx.x * 128, h = blockIdx.y, b = blockIdx.z;
    const size_t head = ((size_t)b * HH + h) * SS * HD;

    const __half* Qp  = g_Qh + head + (size_t)q0 * HD;
    const __half* Khp = g_Kh + head;
    const __half* Vhp = g_Vh + head;

    #define LOAD_KV(t, s) do {                                                  \
        const int _k0 = (t) * 64;                                               \
        const __half* _pl[2] = {Khp, Vhp};                                      \
        const unsigned _b = sb + QPL + (s) * STG;                               \
        _Pragma("unroll")                                                       \
        for (int _it = 0; _it < 4; _it++) {                                     \
            const int _c = _it * 256 + tid;                                     \
            const int _p = _c >> 9, _r = (_c >> 3) & 63, _ch = _c & 7;          \
            cp16(_b + _p * KPL + _r * (RSA*2) + _ch * 16,                       \
                 _pl[_p] + (size_t)(_k0 + _r) * HD + _ch * 8);                  \
        }                                                                       \
        asm volatile("cp.async.commit_group;" ::: "memory");                    \
    } while (0)

    // prologue: Q plane + stage 0
    #pragma unroll
    for (int it = 0; it < 4; it++) {
        const int c = it * 256 + tid;          // 0..1023
        const int row = (c >> 3) & 127, ch = c & 7;
        cp16(sb + row * (RSA*2) + ch * 16, Qp + (size_t)row * HD + ch * 8);
    }
    LOAD_KV(0, 0);

    float o[8][4];
    #pragma unroll
    for (int u = 0; u < 8; u++)
        #pragma unroll
        for (int j = 0; j < 4; j++) o[u][j] = 0.f;
    float rs0 = 0.f, rs1 = 0.f;
    unsigned qh[4][4];

    const int r0a = q0 + wid * 16 + (lane >> 2);
    const int r1a = r0a + 8;

    for (int t = 0; t < SS / 64; t++) {
        if (t + 1 < SS / 64) {
            LOAD_KV(t + 1, (t + 1) & 1);
            asm volatile("cp.async.wait_group 1;" ::: "memory");
        } else {
            asm volatile("cp.async.wait_group 0;" ::: "memory");
        }
        __syncthreads();

        if (t == 0) {   // Q fragments -> registers, once
            #pragma unroll
            for (int kk = 0; kk < 4; kk++) {
                const int row = wid * 16 + (lane & 15);
                const unsigned off = row * (RSA*2) + (kk * 16 + (lane >> 4) * 8) * 2;
                ldm4(qh[kk][0], qh[kk][1], qh[kk][2], qh[kk][3], sb + off);
            }
        }

        const unsigned st = sb + QPL + (t & 1) * STG;
        const uint2 mw0 = *(const uint2*)&g_bm[r0a * (SS/32) + t * 2];
        const uint2 mw1 = *(const uint2*)&g_bm[r1a * (SS/32) + t * 2];

        // ---- S = Q K^T ----
        float s[8][4];
        #pragma unroll
        for (int j = 0; j < 8; j++)
            #pragma unroll
            for (int e = 0; e < 4; e++) s[j][e] = 0.f;

        #pragma unroll
        for (int kk = 0; kk < 4; kk++) {
            #pragma unroll
            for (int p = 0; p < 4; p++) {
                unsigned bh2[2][2];
                const int g = lane >> 3;
                const int row = p * 16 + ((g >> 1) << 3) + (lane & 7);
                const unsigned off = row * (RSA*2) + (kk * 16 + (g & 1) * 8) * 2;
                ldm4(bh2[0][0], bh2[0][1], bh2[1][0], bh2[1][1], st + off);
                mma16816h(s[2*p],   qh[kk], bh2[0]);
                mma16816h(s[2*p+1], qh[kk], bh2[1]);
            }
        }

        // ---- softmax numerator ----
        #pragma unroll
        for (int j = 0; j < 8; j++) {
            const int sh = (8 * j + (lane & 3) * 2) & 31;
            const unsigned wA = (j < 4) ? mw0.x : mw0.y;
            const unsigned wB = (j < 4) ? mw1.x : mw1.y;
            s[j][0] = (float)((wA >> sh) & 1u)       * __expf(s[j][0]);
            s[j][1] = (float)((wA >> (sh + 1)) & 1u) * __expf(s[j][1]);
            s[j][2] = (float)((wB >> sh) & 1u)       * __expf(s[j][2]);
            s[j][3] = (float)((wB >> (sh + 1)) & 1u) * __expf(s[j][3]);
            rs0 += s[j][0] + s[j][1];
            rs1 += s[j][2] + s[j][3];
        }

        // ---- O += P V  (fp16 1-term) ----
        #pragma unroll
        for (int t16 = 0; t16 < 4; t16++) {
            unsigned ph[4];
            {
                __half2 a  = __floats2half2_rn(s[2*t16][0],   s[2*t16][1]);
                __half2 b2 = __floats2half2_rn(s[2*t16][2],   s[2*t16][3]);
                __half2 c2 = __floats2half2_rn(s[2*t16+1][0], s[2*t16+1][1]);
                __half2 d2 = __floats2half2_rn(s[2*t16+1][2], s[2*t16+1][3]);
                ph[0] = *reinterpret_cast<unsigned*>(&a);
                ph[1] = *reinterpret_cast<unsigned*>(&b2);
                ph[2] = *reinterpret_cast<unsigned*>(&c2);
                ph[3] = *reinterpret_cast<unsigned*>(&d2);
            }

            #pragma unroll
            for (int u2 = 0; u2 < 4; u2++) {
                unsigned vh[2][2];
                const int g = lane >> 3;
                const int row = t16 * 16 + (g & 1) * 8 + (lane & 7);
                const unsigned off = row * (RSA*2) + (u2 * 16 + (g >> 1) * 8) * 2;
                ldm4t(vh[0][0], vh[0][1], vh[1][0], vh[1][1], st + KPL + off);
                mma16816h(o[2*u2],   ph, vh[0]);
                mma16816h(o[2*u2+1], ph, vh[1]);
            }
        }
        __syncthreads();
    }

    // ---- normalize + write fp16 (x32) to g_Ah ----
    rs0 += __shfl_xor_sync(0xffffffffu, rs0, 1);
    rs0 += __shfl_xor_sync(0xffffffffu, rs0, 2);
    rs1 += __shfl_xor_sync(0xffffffffu, rs1, 1);
    rs1 += __shfl_xor_sync(0xffffffffu, rs1, 2);
    const float inv0 = ASC / rs0, inv1 = ASC / rs1;

    const size_t mr0 = (size_t)(b * SS + r0a) * EE + h * 64;
    const size_t mr1 = (size_t)(b * SS + r1a) * EE + h * 64;
    #pragma unroll
    for (int u = 0; u < 8; u++) {
        const int c = 8 * u + (lane & 3) * 2;
        *reinterpret_cast<__half2*>(&g_Ah[mr0 + c]) =
            __floats2half2_rn(o[u][0] * inv0, o[u][1] * inv0);
        *reinterpret_cast<__half2*>(&g_Ah[mr1 + c]) =
            __floats2half2_rn(o[u][2] * inv1, o[u][3] * inv1);
    }
}

// ---------------------------------------------------------------------------
extern "C" void kernel_launch(void* const* d_in, const int* in_sizes, int n_in,
                              void* d_out, int out_size)
{
    const float* q    = (const float*)d_in[0];
    const float* k    = (const float*)d_in[1];
    const float* v    = (const float*)d_in[2];
    const int*   mask = (const int*)  d_in[3];
    const float* wq   = (const float*)d_in[4];
    const float* wk   = (const float*)d_in[5];
    const float* wv   = (const float*)d_in[6];
    const float* wo   = (const float*)d_in[7];
    const float* bo   = (const float*)d_in[8];
    float* out = (float*)d_out;

    cudaFuncSetAttribute(mm_kernel,   cudaFuncAttributeMaxDynamicSharedMemorySize, SMEM_MM);
    cudaFuncSetAttribute(attn_kernel, cudaFuncAttributeMaxDynamicSharedMemorySize, ASMEM);

    bm_kernel<<<SS*SS/256, 256>>>(mask);

    dim3 gx(MM*EE/1024, 3);
    cvtx_kernel<<<gx, 256>>>(q, k, v);
    dim3 gw(EE*EE/1024, 4);
    cvtw_kernel<<<gw, 256>>>(wq, wk, wv, wo);

    // Q/K/V projections: 1-term fp16, 128x128 tiles
    dim3 gp(EE/128, MM/128, 3);
    mm_kernel<<<gp, 256, SMEM_MM>>>(0, nullptr, bo);

    // Attention
    dim3 ga(SS/128, HH, BB);
    attn_kernel<<<ga, 256, ASMEM>>>();

    // Output projection: 1-term fp16 + bias
    dim3 go(EE/128, MM/128, 1);
    mm_kernel<<<go, 256, SMEM_MM>>>(3, out, bo);
}

// round 17
// speedup vs baseline: 1.6837x; 1.0603x over previous
#include <cuda_runtime.h>
#include <cuda_bf16.h>
#include <cuda_fp16.h>

#define BB 2
#define SS 2048
#define EE 1024
#define HH 16
#define HD 64
#define MM (BB*SS)   // 4096
#define SCALE 0.03125f      // 1/sqrt(1024)
#define WSC 1024.0f         // weight prescale (2^10)
#define ASC 32.0f           // attention-output prescale (2^5)

// ---------------------------------------------------------------------------
// Scratch (__device__ globals — allocation-free)
// ---------------------------------------------------------------------------
__device__ __half g_Xh[3*MM*EE];                   // inputs, fp16
__device__ __half g_Wh[4*EE*EE];                   // weights, fp16, x1024
__device__ __half g_Qh[BB*HH*SS*HD];               // pre-scaled by 1/32
__device__ __half g_Kh[BB*HH*SS*HD];
__device__ __half g_Vh[BB*HH*SS*HD];
__device__ __half g_Ah[MM*EE];                     // attn out, fp16, x32
__device__ unsigned g_bm[SS*SS/32];

// ---------------------------------------------------------------------------
// Helpers
// ---------------------------------------------------------------------------
__device__ __forceinline__ unsigned smem_u32(const void* p) {
    unsigned a;
    asm("{ .reg .u64 t; cvta.to.shared.u64 t, %1; cvt.u32.u64 %0, t; }" : "=r"(a) : "l"(p));
    return a;
}
__device__ __forceinline__ void ldm4(unsigned& r0, unsigned& r1, unsigned& r2, unsigned& r3, unsigned addr) {
    asm volatile("ldmatrix.sync.aligned.m8n8.x4.shared.b16 {%0,%1,%2,%3}, [%4];"
                 : "=r"(r0), "=r"(r1), "=r"(r2), "=r"(r3) : "r"(addr));
}
__device__ __forceinline__ void ldm4t(unsigned& r0, unsigned& r1, unsigned& r2, unsigned& r3, unsigned addr) {
    asm volatile("ldmatrix.sync.aligned.m8n8.x4.trans.shared.b16 {%0,%1,%2,%3}, [%4];"
                 : "=r"(r0), "=r"(r1), "=r"(r2), "=r"(r3) : "r"(addr));
}
__device__ __forceinline__ void mma16816h(float* c, const unsigned* a, const unsigned* b) {
    asm volatile(
        "mma.sync.aligned.m16n8k16.row.col.f32.f16.f16.f32 "
        "{%0,%1,%2,%3}, {%4,%5,%6,%7}, {%8,%9}, {%0,%1,%2,%3};"
        : "+f"(c[0]), "+f"(c[1]), "+f"(c[2]), "+f"(c[3])
        : "r"(a[0]), "r"(a[1]), "r"(a[2]), "r"(a[3]), "r"(b[0]), "r"(b[1]));
}
__device__ __forceinline__ void cp16(unsigned dst, const void* src) {
    asm volatile("cp.async.cg.shared.global [%0], [%1], 16;" :: "r"(dst), "l"(src) : "memory");
}

// ---------------------------------------------------------------------------
// mask int32 [S*S] -> bitmask
// ---------------------------------------------------------------------------
__global__ __launch_bounds__(256) void bm_kernel(const int* __restrict__ mask) {
    const int i = blockIdx.x * 256 + threadIdx.x;
    unsigned b = __ballot_sync(0xffffffffu, mask[i] != 0);
    if ((i & 31) == 0) g_bm[i >> 5] = b;
}

// ---------------------------------------------------------------------------
// fp32 -> fp16 (inputs, fused q/k/v via blockIdx.y)
// ---------------------------------------------------------------------------
__global__ __launch_bounds__(256) void cvtx_kernel(const float* __restrict__ q,
                                                   const float* __restrict__ k,
                                                   const float* __restrict__ v)
{
    const float* src = (blockIdx.y == 0) ? q : (blockIdx.y == 1) ? k : v;
    __half* hi = g_Xh + (size_t)blockIdx.y * MM * EE;
    const size_t i = (size_t)(blockIdx.x * 256 + threadIdx.x) * 4;
    float4 val = *(const float4*)(src + i);
    *reinterpret_cast<__half2*>(&hi[i])     = __floats2half2_rn(val.x, val.y);
    *reinterpret_cast<__half2*>(&hi[i + 2]) = __floats2half2_rn(val.z, val.w);
}

// fp32 -> fp16, prescaled x1024 (weights, fused via blockIdx.y)
__global__ __launch_bounds__(256) void cvtw_kernel(const float* __restrict__ wq,
                                                   const float* __restrict__ wk,
                                                   const float* __restrict__ wv,
                                                   const float* __restrict__ wo)
{
    const float* src = (blockIdx.y == 0) ? wq : (blockIdx.y == 1) ? wk :
                       (blockIdx.y == 2) ? wv : wo;
    __half* hi = g_Wh + (size_t)blockIdx.y * EE * EE;
    const size_t i = (size_t)(blockIdx.x * 256 + threadIdx.x) * 4;
    float4 val = *(const float4*)(src + i);
    *reinterpret_cast<__half2*>(&hi[i])     = __floats2half2_rn(val.x * WSC, val.y * WSC);
    *reinterpret_cast<__half2*>(&hi[i + 2]) = __floats2half2_rn(val.z * WSC, val.w * WSC);
}

// ---------------------------------------------------------------------------
// HMMA fp16 1-term GEMM: C = A @ B^T  (B prescaled x1024)
// CTA 256 thr (8 warps 2x4), tile 128x128, warp tile 64x32, K-chunk 32,
// 3-stage cp.async pipeline (ONE barrier per chunk), 2 CTAs/SM.
// sel 0/1/2: A = X plane -> Q/K/V fp16 planes.  sel 3: A = g_Ah -> fp32 out.
// ---------------------------------------------------------------------------
#define KC 32
#define RS 40
#define TILE_BYTES (128*RS*2)         // 10240
#define STB (2*TILE_BYTES)            // 20480 per stage (A, B)
#define SMEM_MM (3*STB)               // 61440

__global__ __launch_bounds__(256, 2) void mm_kernel(int sel_base, float* __restrict__ out_ext,
                                                    const float* __restrict__ bias)
{
    extern __shared__ __half smM[];
    const unsigned sb = smem_u32(smM);

    const int tid = threadIdx.x;
    const int wid = tid >> 5, lane = tid & 31;
    const int wm = wid >> 2, wn = wid & 3;
    const int m0 = blockIdx.y * 128, n0 = blockIdx.x * 128;
    const int sel = sel_base + blockIdx.z;

    const __half* Ahp = (sel < 3) ? g_Xh + (size_t)sel * MM * EE : g_Ah;
    const __half* Bhp = g_Wh + (size_t)sel * EE * EE;

    float acc[16][4];
    #pragma unroll
    for (int i = 0; i < 16; i++)
        #pragma unroll
        for (int j = 0; j < 4; j++) acc[i][j] = 0.f;

    const int r  = tid >> 2;        // 0..63
    const int ch = tid & 3;

    auto load_stage = [&](int c, int s) {
        const unsigned base = sb + s * STB;
        const __half* Asrc = Ahp + (size_t)m0 * EE + c * KC;
        const __half* Bsrc = Bhp + (size_t)n0 * EE + c * KC;
        #pragma unroll
        for (int i2 = 0; i2 < 2; i2++) {
            const int row = i2 * 64 + r;
            cp16(base + row * (RS*2) + ch * 16, Asrc + (size_t)row * EE + ch * 8);
            cp16(base + TILE_BYTES + row * (RS*2) + ch * 16, Bsrc + (size_t)row * EE + ch * 8);
        }
        asm volatile("cp.async.commit_group;" ::: "memory");
    };

    load_stage(0, 0);
    load_stage(1, 1);

    int sr = 0, sw = 2;
    for (int c = 0; c < EE / KC; c++) {
        if (c < EE / KC - 1)
            asm volatile("cp.async.wait_group 1;" ::: "memory");
        else
            asm volatile("cp.async.wait_group 0;" ::: "memory");
        __syncthreads();

        const unsigned st = sb + sr * STB;
        const unsigned aH = st;
        const unsigned bH = st + TILE_BYTES;

        #pragma unroll
        for (int kk = 0; kk < KC; kk += 16) {
            unsigned ah[4][4];
            #pragma unroll
            for (int i = 0; i < 4; i++) {
                const int row = wm * 64 + 16 * i + (lane & 15);
                const unsigned off = row * (RS*2) + (kk + (lane >> 4) * 8) * 2;
                ldm4(ah[i][0], ah[i][1], ah[i][2], ah[i][3], aH + off);
            }
            unsigned bh[4][2];
            #pragma unroll
            for (int p = 0; p < 2; p++) {
                const int g = lane >> 3;
                const int row = wn * 32 + 16 * p + ((g >> 1) << 3) + (lane & 7);
                const unsigned off = row * (RS*2) + (kk + (g & 1) * 8) * 2;
                ldm4(bh[2*p][0], bh[2*p][1], bh[2*p+1][0], bh[2*p+1][1], bH + off);
            }
            #pragma unroll
            for (int i = 0; i < 4; i++)
                #pragma unroll
                for (int j = 0; j < 4; j++)
                    mma16816h(acc[i*4+j], ah[i], bh[j]);
        }

        if (c + 2 < EE / KC)
            load_stage(c + 2, sw);

        sr = (sr == 2) ? 0 : sr + 1;
        sw = (sw == 2) ? 0 : sw + 1;
    }

    const float DSC  = 1.0f / WSC;            // descale weights
    const float DSCO = 1.0f / (WSC * ASC);    // descale weights + A prescale

    #pragma unroll
    for (int i = 0; i < 4; i++) {
        #pragma unroll
        for (int j = 0; j < 4; j++) {
            const int n = n0 + wn * 32 + 8 * j + (lane & 3) * 2;
            #pragma unroll
            for (int hrow = 0; hrow < 2; hrow++) {
                const int m = m0 + wm * 64 + 16 * i + (lane >> 2) + hrow * 8;
                float2 val = make_float2(acc[i*4+j][hrow*2+0], acc[i*4+j][hrow*2+1]);
                if (sel < 3) {
                    val.x *= DSC; val.y *= DSC;
                    const int b = m >> 11, s = m & (SS - 1);
                    const int h = n >> 6, dd = n & 63;
                    const size_t off = (((size_t)b * HH + h) * SS + s) * HD + dd;
                    if (sel == 0) {
                        *reinterpret_cast<__half2*>(&g_Qh[off]) =
                            __floats2half2_rn(val.x * SCALE, val.y * SCALE);
                    } else if (sel == 1) {
                        *reinterpret_cast<__half2*>(&g_Kh[off]) = __floats2half2_rn(val.x, val.y);
                    } else {
                        *reinterpret_cast<__half2*>(&g_Vh[off]) = __floats2half2_rn(val.x, val.y);
                    }
                } else {
                    val.x = val.x * DSCO + bias[n];
                    val.y = val.y * DSCO + bias[n + 1];
                    *(float2*)(out_ext + (size_t)m * EE + n) = val;
                }
            }
        }
    }
}

// ---------------------------------------------------------------------------
// Tensor-core flash attention: fp16 1-term QK^T, fp16 1-term PV,
// no-max softmax. Grid (SS/128, HH, BB), 256 thr (8 warps x 16 q-rows),
// 3-stage KV pipeline (ONE barrier per tile), 2 CTAs/SM.
// ---------------------------------------------------------------------------
#define RSA 72
#define QPL (128*RSA*2)        // 18432 B  (Q fp16, pre-scaled)
#define KPL (64*RSA*2)         // 9216 B per K/V plane
#define STG (2*KPL)            // 18432 B per stage (Kh, Vh)
#define ASMEM (QPL + 3*STG)    // 73728 B

__global__ __launch_bounds__(256, 2) void attn_kernel()
{
    extern __shared__ __half smA[];
    const unsigned sb = smem_u32(smA);
    const int tid = threadIdx.x, wid = tid >> 5, lane = tid & 31;
    const int q0 = blockIdx.x * 128, h = blockIdx.y, b = blockIdx.z;
    const size_t head = ((size_t)b * HH + h) * SS * HD;

    const __half* Qp  = g_Qh + head + (size_t)q0 * HD;
    const __half* Khp = g_Kh + head;
    const __half* Vhp = g_Vh + head;

    #define LOAD_KV(t, s) do {                                                  \
        const int _k0 = (t) * 64;                                               \
        const __half* _pl[2] = {Khp, Vhp};                                      \
        const unsigned _b = sb + QPL + (s) * STG;                               \
        _Pragma("unroll")                                                       \
        for (int _it = 0; _it < 4; _it++) {                                     \
            const int _c = _it * 256 + tid;                                     \
            const int _p = _c >> 9, _r = (_c >> 3) & 63, _ch = _c & 7;          \
            cp16(_b + _p * KPL + _r * (RSA*2) + _ch * 16,                       \
                 _pl[_p] + (size_t)(_k0 + _r) * HD + _ch * 8);                  \
        }                                                                       \
        asm volatile("cp.async.commit_group;" ::: "memory");                    \
    } while (0)

    // prologue: Q plane + stage 0 (one group), then stage 1
    #pragma unroll
    for (int it = 0; it < 4; it++) {
        const int c = it * 256 + tid;          // 0..1023
        const int row = (c >> 3) & 127, ch = c & 7;
        cp16(sb + row * (RSA*2) + ch * 16, Qp + (size_t)row * HD + ch * 8);
    }
    LOAD_KV(0, 0);
    LOAD_KV(1, 1);

    float o[8][4];
    #pragma unroll
    for (int u = 0; u < 8; u++)
        #pragma unroll
        for (int j = 0; j < 4; j++) o[u][j] = 0.f;
    float rs0 = 0.f, rs1 = 0.f;
    unsigned qh[4][4];

    const int r0a = q0 + wid * 16 + (lane >> 2);
    const int r1a = r0a + 8;

    int sr = 0, sw = 2;
    for (int t = 0; t < SS / 64; t++) {
        if (t < SS / 64 - 1)
            asm volatile("cp.async.wait_group 1;" ::: "memory");
        else
            asm volatile("cp.async.wait_group 0;" ::: "memory");
        __syncthreads();

        if (t == 0) {   // Q fragments -> registers, once
            #pragma unroll
            for (int kk = 0; kk < 4; kk++) {
                const int row = wid * 16 + (lane & 15);
                const unsigned off = row * (RSA*2) + (kk * 16 + (lane >> 4) * 8) * 2;
                ldm4(qh[kk][0], qh[kk][1], qh[kk][2], qh[kk][3], sb + off);
            }
        }

        const unsigned st = sb + QPL + sr * STG;
        const uint2 mw0 = *(const uint2*)&g_bm[r0a * (SS/32) + t * 2];
        const uint2 mw1 = *(const uint2*)&g_bm[r1a * (SS/32) + t * 2];

        // ---- S = Q K^T ----
        float s[8][4];
        #pragma unroll
        for (int j = 0; j < 8; j++)
            #pragma unroll
            for (int e = 0; e < 4; e++) s[j][e] = 0.f;

        #pragma unroll
        for (int kk = 0; kk < 4; kk++) {
            #pragma unroll
            for (int p = 0; p < 4; p++) {
                unsigned bh2[2][2];
                const int g = lane >> 3;
                const int row = p * 16 + ((g >> 1) << 3) + (lane & 7);
                const unsigned off = row * (RSA*2) + (kk * 16 + (g & 1) * 8) * 2;
                ldm4(bh2[0][0], bh2[0][1], bh2[1][0], bh2[1][1], st + off);
                mma16816h(s[2*p],   qh[kk], bh2[0]);
                mma16816h(s[2*p+1], qh[kk], bh2[1]);
            }
        }

        // ---- softmax numerator ----
        #pragma unroll
        for (int j = 0; j < 8; j++) {
            const int sh = (8 * j + (lane & 3) * 2) & 31;
            const unsigned wA = (j < 4) ? mw0.x : mw0.y;
            const unsigned wB = (j < 4) ? mw1.x : mw1.y;
            s[j][0] = (float)((wA >> sh) & 1u)       * __expf(s[j][0]);
            s[j][1] = (float)((wA >> (sh + 1)) & 1u) * __expf(s[j][1]);
            s[j][2] = (float)((wB >> sh) & 1u)       * __expf(s[j][2]);
            s[j][3] = (float)((wB >> (sh + 1)) & 1u) * __expf(s[j][3]);
            rs0 += s[j][0] + s[j][1];
            rs1 += s[j][2] + s[j][3];
        }

        // ---- O += P V  (fp16 1-term) ----
        #pragma unroll
        for (int t16 = 0; t16 < 4; t16++) {
            unsigned ph[4];
            {
                __half2 a  = __floats2half2_rn(s[2*t16][0],   s[2*t16][1]);
                __half2 b2 = __floats2half2_rn(s[2*t16][2],   s[2*t16][3]);
                __half2 c2 = __floats2half2_rn(s[2*t16+1][0], s[2*t16+1][1]);
                __half2 d2 = __floats2half2_rn(s[2*t16+1][2], s[2*t16+1][3]);
                ph[0] = *reinterpret_cast<unsigned*>(&a);
                ph[1] = *reinterpret_cast<unsigned*>(&b2);
                ph[2] = *reinterpret_cast<unsigned*>(&c2);
                ph[3] = *reinterpret_cast<unsigned*>(&d2);
            }

            #pragma unroll
            for (int u2 = 0; u2 < 4; u2++) {
                unsigned vh[2][2];
                const int g = lane >> 3;
                const int row = t16 * 16 + (g & 1) * 8 + (lane & 7);
                const unsigned off = row * (RSA*2) + (u2 * 16 + (g >> 1) * 8) * 2;
                ldm4t(vh[0][0], vh[0][1], vh[1][0], vh[1][1], st + KPL + off);
                mma16816h(o[2*u2],   ph, vh[0]);
                mma16816h(o[2*u2+1], ph, vh[1]);
            }
        }

        if (t + 2 < SS / 64)
            LOAD_KV(t + 2, sw);

        sr = (sr == 2) ? 0 : sr + 1;
        sw = (sw == 2) ? 0 : sw + 1;
    }

    // ---- normalize + write fp16 (x32) to g_Ah ----
    rs0 += __shfl_xor_sync(0xffffffffu, rs0, 1);
    rs0 += __shfl_xor_sync(0xffffffffu, rs0, 2);
    rs1 += __shfl_xor_sync(0xffffffffu, rs1, 1);
    rs1 += __shfl_xor_sync(0xffffffffu, rs1, 2);
    const float inv0 = ASC / rs0, inv1 = ASC / rs1;

    const size_t mr0 = (size_t)(b * SS + r0a) * EE + h * 64;
    const size_t mr1 = (size_t)(b * SS + r1a) * EE + h * 64;
    #pragma unroll
    for (int u = 0; u < 8; u++) {
        const int c = 8 * u + (lane & 3) * 2;
        *reinterpret_cast<__half2*>(&g_Ah[mr0 + c]) =
            __floats2half2_rn(o[u][0] * inv0, o[u][1] * inv0);
        *reinterpret_cast<__half2*>(&g_Ah[mr1 + c]) =
            __floats2half2_rn(o[u][2] * inv1, o[u][3] * inv1);
    }
}

// ---------------------------------------------------------------------------
extern "C" void kernel_launch(void* const* d_in, const int* in_sizes, int n_in,
                              void* d_out, int out_size)
{
    const float* q    = (const float*)d_in[0];
    const float* k    = (const float*)d_in[1];
    const float* v    = (const float*)d_in[2];
    const int*   mask = (const int*)  d_in[3];
    const float* wq   = (const float*)d_in[4];
    const float* wk   = (const float*)d_in[5];
    const float* wv   = (const float*)d_in[6];
    const float* wo   = (const float*)d_in[7];
    const float* bo   = (const float*)d_in[8];
    float* out = (float*)d_out;

    cudaFuncSetAttribute(mm_kernel,   cudaFuncAttributeMaxDynamicSharedMemorySize, SMEM_MM);
    cudaFuncSetAttribute(attn_kernel, cudaFuncAttributeMaxDynamicSharedMemorySize, ASMEM);

    bm_kernel<<<SS*SS/256, 256>>>(mask);

    dim3 gx(MM*EE/1024, 3);
    cvtx_kernel<<<gx, 256>>>(q, k, v);
    dim3 gw(EE*EE/1024, 4);
    cvtw_kernel<<<gw, 256>>>(wq, wk, wv, wo);

    // Q/K/V projections: 1-term fp16, 128x128 tiles
    dim3 gp(EE/128, MM/128, 3);
    mm_kernel<<<gp, 256, SMEM_MM>>>(0, nullptr, bo);

    // Attention
    dim3 ga(SS/128, HH, BB);
    attn_kernel<<<ga, 256, ASMEM>>>();

    // Output projection: 1-term fp16 + bias
    dim3 go(EE/128, MM/128, 1);
    mm_kernel<<<go, 256, SMEM_MM>>>(3, out, bo);
}